// round 12
// baseline (speedup 1.0000x reference)
#include <cuda_runtime.h>

// TTD_TransE_TYPE scoring — FINAL converged kernel.
// Floor of 6.624us reproduced 5x exactly (R1, R5, R7, R8, R11); run-to-run
// noise ±0.25us (R10 byte-identical rerun). Search space exhausted:
// block/grid shape, occupancy 19-77%, cache policies, per-warp ILP 1-4,
// reduce variants (sm_103 has no fp32 redux), epilogue forms — all flat.
// Binding terms: launch/replay overhead + the intrinsic 3-level dependent
// gather chain (sample -> node_type -> matrix rows), TLP-hidden; all
// throughput rooflines >=4x away (DRAM 15%, L2 10%, issue 22%).
//
// Inputs (metadata order):
//   d_in[0] sample       int32  [B,3]      (head, rel, tail)
//   d_in[1] entity_emb   f32    [E,128]
//   d_in[2] relation_emb f32    [R,128]    (unused by the math)
//   d_in[3] type_emb     f32    [T*R, 128*128]
//   d_in[4] node_type    int32  [E]
// Output: f32 [B] scores.
//
// Algebra 1: score = |he0 + he1 - he2 + 1e-6| where he_i is the elementwise-
// normalized i-th component of Mh@h -> only matrix rows 0..2 are needed
// (3 dot products per sample instead of a 128x128 GEMV; 42x traffic cut).
// Algebra 2: s / max(|s|, 1e-12) == copysign(min(|s|*1e12, 1), s) exactly
// -> no division/MUFU in the epilogue.

#define D    128
#define TLEN 16   // T = type_emb rows / R

__global__ __launch_bounds__(256, 8) void ttd_transe_kernel(
    const int*   __restrict__ sample,
    const float* __restrict__ entity_emb,
    const float* __restrict__ type_emb,
    const int*   __restrict__ node_type,
    float*       __restrict__ out)
{
    const int gwarp = (blockIdx.x << 3) + (threadIdx.x >> 5);
    const int lane  = threadIdx.x & 31;

    // Level 1: sample indices (lane-uniform -> one broadcast transaction each).
    const int head = __ldg(&sample[gwarp * 3 + 0]);
    const int rel  = __ldg(&sample[gwarp * 3 + 1]);

    // Level 2: node_type gather + entity row issued together; the
    // rel-dependent matrix base is formed while node_type is in flight so a
    // single IMAD remains on the critical path after the gather lands.
    const int nt = __ldg(&node_type[head]);
    const float4* __restrict__ h4 =
        reinterpret_cast<const float4*>(entity_emb) + head * (D / 4);
    const float4 hv = __ldg(&h4[lane]);

    const float4* __restrict__ m4 =
        reinterpret_cast<const float4*>(type_emb)
        + rel * (TLEN * D * D / 4) + nt * (D * D / 4);

    // Level 3: matrix rows 0..2 — three coalesced 512B warp loads.
    const float4 r0 = __ldg(&m4[lane]);
    const float4 r1 = __ldg(&m4[32 + lane]);
    const float4 r2 = __ldg(&m4[64 + lane]);

    float s0 = fmaf(hv.x, r0.x, fmaf(hv.y, r0.y, fmaf(hv.z, r0.z, hv.w * r0.w)));
    float s1 = fmaf(hv.x, r1.x, fmaf(hv.y, r1.y, fmaf(hv.z, r1.z, hv.w * r1.w)));
    float s2 = fmaf(hv.x, r2.x, fmaf(hv.y, r2.y, fmaf(hv.z, r2.z, hv.w * r2.w)));

    // 5-level butterfly: 15 SHFLs — minimal warp-wide fp32 sum on sm_103;
    // dependent depth hidden by warp switching at ~71% occupancy.
    #pragma unroll
    for (int off = 16; off > 0; off >>= 1) {
        s0 += __shfl_xor_sync(0xFFFFFFFFu, s0, off);
        s1 += __shfl_xor_sync(0xFFFFFFFFu, s1, off);
        s2 += __shfl_xor_sync(0xFFFFFFFFu, s2, off);
    }

    if (lane == 0) {
        // Exact branchless form of s / max(|s|, 1e-12).
        const float a = copysignf(fminf(fabsf(s0) * 1e12f, 1.0f), s0);
        const float b = copysignf(fminf(fabsf(s1) * 1e12f, 1.0f), s1);
        const float c = copysignf(fminf(fabsf(s2) * 1e12f, 1.0f), s2);
        out[gwarp] = fabsf(a + b - c + 1e-6f);
    }
}

extern "C" void kernel_launch(void* const* d_in, const int* in_sizes, int n_in,
                              void* d_out, int out_size)
{
    const int*   sample     = (const int*)  d_in[0];
    const float* entity_emb = (const float*)d_in[1];
    // d_in[2] relation_emb unused by the score
    const float* type_emb   = (const float*)d_in[3];
    const int*   node_type  = (const int*)  d_in[4];
    float* out = (float*)d_out;

    const int B = out_size;                 // 8192, multiple of 8
    const int threads = 256;                // 8 warps/block, one warp/sample
    const int blocks = B / 8;               // 1024 — single full wave

    ttd_transe_kernel<<<blocks, threads>>>(sample, entity_emb, type_emb,
                                           node_type, out);
}